// round 15
// baseline (speedup 1.0000x reference)
#include <cuda_runtime.h>
#include <cuda_fp16.h>
#include <cstdint>

// Problem constants (fixed shapes from reference)
#define Bz 8
#define Tz 1024
#define Cz 1024
#define Hz 16
#define Dz 64
#define Mz (Bz*Tz)   // 8192

// ---- mma / ldmatrix / cp.async helpers (arch-agnostic PTX) -----------------
__device__ __forceinline__ uint32_t smem_to_u32(const void* p) {
    uint32_t a;
    asm("{ .reg .u64 t; cvta.to.shared.u64 t, %1; cvt.u32.u64 %0, t; }" : "=r"(a) : "l"(p));
    return a;
}
__device__ __forceinline__ void ldm4(uint32_t* r, uint32_t addr) {
    asm volatile("ldmatrix.sync.aligned.m8n8.x4.shared.b16 {%0,%1,%2,%3}, [%4];"
                 : "=r"(r[0]), "=r"(r[1]), "=r"(r[2]), "=r"(r[3]) : "r"(addr));
}
__device__ __forceinline__ void ldm4t(uint32_t* r, uint32_t addr) {
    asm volatile("ldmatrix.sync.aligned.m8n8.x4.trans.shared.b16 {%0,%1,%2,%3}, [%4];"
                 : "=r"(r[0]), "=r"(r[1]), "=r"(r[2]), "=r"(r[3]) : "r"(addr));
}
__device__ __forceinline__ void mma_f16(float* c, const uint32_t* a, const uint32_t* b) {
    asm volatile("mma.sync.aligned.m16n8k16.row.col.f32.f16.f16.f32 "
                 "{%0,%1,%2,%3},{%4,%5,%6,%7},{%8,%9},{%0,%1,%2,%3};"
                 : "+f"(c[0]), "+f"(c[1]), "+f"(c[2]), "+f"(c[3])
                 : "r"(a[0]), "r"(a[1]), "r"(a[2]), "r"(a[3]), "r"(b[0]), "r"(b[1]));
}
__device__ __forceinline__ void cp16(uint32_t s, const void* g) {
    asm volatile("cp.async.cg.shared.global [%0], [%1], 16;" :: "r"(s), "l"(g));
}
#define CP_COMMIT() asm volatile("cp.async.commit_group;" ::: "memory")
#define CP_WAIT0()  asm volatile("cp.async.wait_group 0;" ::: "memory")

// ---- scratch (device globals; no allocation allowed) -----------------------
__device__ __align__(16) __half g_qh[Bz*Hz*Tz*Dz];   // [b][h][t][d] fp16
__device__ __align__(16) __half g_kh[Bz*Hz*Tz*Dz];
__device__ __align__(16) __half g_vh[Bz*Hz*Tz*Dz];
__device__ __align__(16) __half g_yh[Mz*Cz];         // attn out fp16, [m][h*64+d]
__device__ __align__(16) __half g_xh[Mz*Cz];         // x fp16, [M][1024]
__device__ __align__(16) __half g_wqkvh[3*Cz*Cz];    // Wqkv^T fp16 [3072][1024]
__device__ __align__(16) __half g_wprjh[Cz*Cz];      // Wproj^T fp16 [1024][1024]

// ---------------------------------------------------------------------------
// Prep: x fp32 -> fp16
// ---------------------------------------------------------------------------
__global__ void __launch_bounds__(256) cvt_x_kernel(const float* __restrict__ in)
{
    const int n4 = Mz*Cz/4;
    for (int i = blockIdx.x * blockDim.x + threadIdx.x; i < n4; i += gridDim.x * blockDim.x) {
        float4 v = ((const float4*)in)[i];
        __half2 h0 = __floats2half2_rn(v.x, v.y);
        __half2 h1 = __floats2half2_rn(v.z, v.w);
        ((uint2*)g_xh)[i] = make_uint2(*(uint32_t*)&h0, *(uint32_t*)&h1);
    }
}

// ---------------------------------------------------------------------------
// Prep: W [1024 k][N n] fp32 -> Wt [N][1024] fp16 (transpose + convert)
// ---------------------------------------------------------------------------
__global__ void __launch_bounds__(256) transpose_cvt_kernel(
    const float* __restrict__ W, int N, int which)
{
    __shared__ float t[32][33];
    __half* T = which ? g_wprjh : g_wqkvh;
    const int n0 = blockIdx.x * 32, k0 = blockIdx.y * 32;
    const int tx = threadIdx.x, ty = threadIdx.y;   // (32, 8)
    #pragma unroll
    for (int j = ty; j < 32; j += 8)
        t[j][tx] = W[(size_t)(k0 + j) * N + n0 + tx];
    __syncthreads();
    #pragma unroll
    for (int j = ty; j < 32; j += 8)
        T[(size_t)(n0 + j) * 1024 + k0 + tx] = __float2half(t[tx][j]);
}

// ---------------------------------------------------------------------------
// fp16 GEMM via mma.sync:  out[M,N] = A[M,1024] x Bt[N,1024]^T + bias
// CTA tile 128x256, BK=32 (2 k16 steps/stage), 2-stage cp.async pipeline,
// ONE barrier per stage (32 barriers total).
// Smem: rows of 64B (4 chunks of 16B), swizzle slot = c ^ ((row>>1)&3).
//   stage = A(128*64) + B(256*64) = 24576 B; 2 stages = 49152 B (48KB exactly).
// 8 warps as 2(m) x 4(n), warp tile 64x64.
// ---------------------------------------------------------------------------
#define STG_A32 8192          // 128 rows * 64B
#define STG32   24576         // A + B(256*64)

__global__ void __launch_bounds__(256) mma_gemm_kernel(
    int mode, int N, const float* __restrict__ bias, float* __restrict__ out)
{
    __shared__ __align__(16) char smem[2*STG32];   // 49152 B

    const int tid  = threadIdx.x;
    const int lane = tid & 31;
    const int wid  = tid >> 5;
    const int warp_m = wid & 1;        // 2 m-warps (64 rows each)
    const int warp_n = wid >> 1;       // 4 n-warps (64 cols each)
    const int m0 = blockIdx.y * 128;
    const int n0 = blockIdx.x * 256;

    const __half* Ap = mode ? g_yh : g_xh;
    const __half* Bp = mode ? g_wprjh : g_wqkvh;

    // ---- staging indices ----
    // A: thread t -> row = t>>1 (0..127), chunk base cb = (t&1)*2 (2 chunks)
    const int arow = tid >> 1;
    const int acb  = (tid & 1) * 2;
    const __half* gA = Ap + (size_t)(m0 + arow) * 1024 + acb*8;   // +8 halves per chunk
    const int aswz = (arow >> 1) & 3;
    const uint32_t stA0 = (uint32_t)(arow*64 + ((acb   ^ aswz)*16));
    const uint32_t stA1 = (uint32_t)(arow*64 + (((acb+1) ^ aswz)*16));
    // B: thread t -> row = t (0..255), 4 chunks
    const __half* gB = Bp + (size_t)(n0 + tid) * 1024;
    const int bswz = (tid >> 1) & 3;
    uint32_t stB[4];
    #pragma unroll
    for (int c = 0; c < 4; c++)
        stB[c] = (uint32_t)(STG_A32 + tid*64 + ((c ^ bswz)*16));

    const uint32_t sbase = smem_to_u32(smem);

    // ---- ldmatrix per-lane addresses ----
    const int rbA = warp_m*64 + (lane & 7) + 8*((lane >> 3) & 1);
    const int hcA = (lane >> 4) & 1;           // 16B half within k16
    const int swA = (rbA >> 1) & 3;            // constant across mi (16*mi)
    const int rbB = warp_n*64 + (lane & 7) + 8*((lane >> 4) & 1);
    const int hcB = (lane >> 3) & 1;
    const int swB = (rbB >> 1) & 3;

    float acc[4][8][4];
    #pragma unroll
    for (int i = 0; i < 4; i++)
        #pragma unroll
        for (int j = 0; j < 8; j++)
            #pragma unroll
            for (int r = 0; r < 4; r++) acc[i][j][r] = 0.f;

    // prologue: stage chunk 0 into buffer 0
    cp16(sbase + stA0, gA);
    cp16(sbase + stA1, gA + 8);
    #pragma unroll
    for (int c = 0; c < 4; c++)
        cp16(sbase + stB[c], gB + c*8);
    CP_COMMIT();

    for (int kc = 0; kc < 32; kc++) {
        CP_WAIT0();          // stage kc retired (only pending group)
        __syncthreads();     // visible to all; readers of other buffer done

        if (kc < 31) {
            const uint32_t so = (uint32_t)((kc+1) & 1) * STG32;
            const int go = (kc+1) * 32;   // halves per BK=32 step
            cp16(sbase + so + stA0, gA + go);
            cp16(sbase + so + stA1, gA + go + 8);
            #pragma unroll
            for (int c = 0; c < 4; c++)
                cp16(sbase + so + stB[c], gB + go + c*8);
        }
        CP_COMMIT();

        const uint32_t bufo = (uint32_t)(kc & 1) * STG32;

        #pragma unroll
        for (int j = 0; j < 2; j++) {     // two k16 steps per stage
            const int cA = 2*j + hcA;
            const int cB = 2*j + hcB;

            uint32_t bf[4][4];
            #pragma unroll
            for (int p = 0; p < 4; p++)
                ldm4(bf[p], sbase + bufo + STG_A32 +
                     (uint32_t)((rbB + 16*p)*64 + ((cB ^ swB)*16)));

            uint32_t af[2][4];
            ldm4(af[0], sbase + bufo + (uint32_t)(rbA*64 + ((cA ^ swA)*16)));
            #pragma unroll
            for (int mi = 0; mi < 4; mi++) {
                if (mi < 3)
                    ldm4(af[(mi+1) & 1], sbase + bufo +
                         (uint32_t)((rbA + 16*(mi+1))*64 + ((cA ^ swA)*16)));
                #pragma unroll
                for (int ni = 0; ni < 8; ni++)
                    mma_f16(acc[mi][ni], af[mi & 1], &bf[ni >> 1][2*(ni & 1)]);
            }
        }
    }

    // Epilogue: bias + store
    const int g4 = lane >> 2;
    const int c2 = 2 * (lane & 3);
    #pragma unroll
    for (int mi = 0; mi < 4; mi++) {
        #pragma unroll
        for (int ni = 0; ni < 8; ni++) {
            int m = m0 + warp_m*64 + mi*16 + g4;
            int n = n0 + warp_n*64 + ni*8 + c2;
            float2 bv = *(const float2*)&bias[n];
            float2 v0 = make_float2(acc[mi][ni][0] + bv.x, acc[mi][ni][1] + bv.y);
            float2 v1 = make_float2(acc[mi][ni][2] + bv.x, acc[mi][ni][3] + bv.y);
            if (mode == 1) {
                *(float2*)&out[(size_t)m * N + n]     = v0;
                *(float2*)&out[(size_t)(m+8) * N + n] = v1;
            } else {
                int which = n >> 10;            // 0=q 1=k 2=v
                int h = (n >> 6) & 15;
                int d = n & 63;
                __half* dst = (which == 0) ? g_qh : ((which == 1) ? g_kh : g_vh);
                int b0i = m >> 10,  t0 = m & 1023;
                int b1i = (m+8) >> 10, t1 = (m+8) & 1023;
                __half2 h0 = __floats2half2_rn(v0.x, v0.y);
                __half2 h1 = __floats2half2_rn(v1.x, v1.y);
                *(__half2*)&dst[((size_t)(b0i*Hz + h)*Tz + t0)*Dz + d] = h0;
                *(__half2*)&dst[((size_t)(b1i*Hz + h)*Tz + t1)*Dz + d] = h1;
            }
        }
    }
}

// ---------------------------------------------------------------------------
// Flash attention v2 (causal), all-fp16 tensor-core path — EXACT R12 version
// (best measured). 64 q-rows per CTA, 4 warps; K/V cp.async double-buffered,
// ONE barrier per k-block.
// ---------------------------------------------------------------------------
#define ASTRIDE 72
#define ATILE (64*ASTRIDE)    // halves per tile (9216 B)

__global__ void __launch_bounds__(128) attn_kernel()
{
    __shared__ __align__(16) __half sT[2][ATILE];
    __shared__ __align__(16) __half sV[2][ATILE];

    const int tid  = threadIdx.x;
    const int lane = tid & 31;
    const int w    = tid >> 5;         // 0..3
    const int qb   = blockIdx.x;
    const int bh   = blockIdx.y;
    const int q0   = qb * 64;

    const uint32_t aT[2] = { smem_to_u32(sT[0]), smem_to_u32(sT[1]) };
    const uint32_t aV[2] = { smem_to_u32(sV[0]), smem_to_u32(sV[1]) };

    // ---- load Q tile into sT[0] (plain copy), hoist frags ----
    {
        const uint4* qg = (const uint4*)(g_qh + ((size_t)bh*Tz + q0)*Dz);
        #pragma unroll
        for (int u = 0; u < 4; u++) {
            int idx4 = tid + 128*u;
            int r = idx4 >> 3, d8 = idx4 & 7;
            *(uint4*)&sT[0][r*ASTRIDE + d8*8] = qg[idx4];
        }
    }
    __syncthreads();

    uint32_t qf[4][4];
    {
        const int rowA = 16*w + (lane & 7) + 8*((lane >> 3) & 1);
        const int colb = ((lane >> 4) & 1) * 16;
        #pragma unroll
        for (int j = 0; j < 4; j++)
            ldm4(qf[j], aT[0] + (uint32_t)(rowA*144 + j*32 + colb));
    }
    __syncthreads();   // Q smem dead; cp.async may overwrite sT[0]

    // ---- prologue: issue K/V for kb=0 into buffer 0 ----
    {
        const __half* kg = g_kh + (size_t)bh*Tz*Dz;
        const __half* vg = g_vh + (size_t)bh*Tz*Dz;
        #pragma unroll
        for (int u = 0; u < 4; u++) {
            int idx4 = tid + 128*u;
            int r = idx4 >> 3, d8 = idx4 & 7;
            uint32_t so = (uint32_t)(r*144 + d8*16);
            cp16(aT[0] + so, kg + idx4*8);
            cp16(aV[0] + so, vg + idx4*8);
        }
        CP_COMMIT();
    }

    float mr[2] = {-1e30f, -1e30f};
    float lr[2] = {0.f, 0.f};
    float O[8][4];
    #pragma unroll
    for (int aI = 0; aI < 8; aI++)
        #pragma unroll
        for (int e = 0; e < 4; e++) O[aI][e] = 0.f;

    const int r0loc = 16*w + (lane >> 2);   // block-local row for softmax/mask

    for (int kb = 0; kb <= qb; kb++) {
        CP_WAIT0();
        __syncthreads();

        // prefetch kb+1 into the other buffer (its readers finished last iter)
        if (kb < qb) {
            const int nb = (kb + 1) & 1;
            const __half* kg = g_kh + ((size_t)bh*Tz + (kb+1)*64)*Dz;
            const __half* vg = g_vh + ((size_t)bh*Tz + (kb+1)*64)*Dz;
            #pragma unroll
            for (int u = 0; u < 4; u++) {
                int idx4 = tid + 128*u;
                int r = idx4 >> 3, d8 = idx4 & 7;
                uint32_t so = (uint32_t)(r*144 + d8*16);
                cp16(aT[nb] + so, kg + idx4*8);
                cp16(aV[nb] + so, vg + idx4*8);
            }
            CP_COMMIT();
        }

        const uint32_t a0 = aT[kb & 1];
        const uint32_t av = aV[kb & 1];

        // ---- S = Q K^T (single fp16 pass) ----
        float S[8][4];
        #pragma unroll
        for (int aI = 0; aI < 8; aI++)
            #pragma unroll
            for (int e = 0; e < 4; e++) S[aI][e] = 0.f;

        const int rowB = (lane & 7) + 8*((lane >> 4) & 1);
        const int colbB = ((lane >> 3) & 1) * 16;
        #pragma unroll
        for (int j = 0; j < 4; j++) {
            #pragma unroll
            for (int p = 0; p < 4; p++) {
                uint32_t kf[4];
                ldm4(kf, a0 + (uint32_t)((16*p + rowB)*144 + j*32 + colbB));
                mma_f16(S[2*p],   qf[j], kf);
                mma_f16(S[2*p+1], qf[j], kf + 2);
            }
        }

        // ---- scale + causal mask (diagonal block only) ----
        const float sc = 0.125f;
        #pragma unroll
        for (int aI = 0; aI < 8; aI++) {
            int colb0 = 16*(aI >> 1) + 8*(aI & 1) + 2*(lane & 3);
            #pragma unroll
            for (int e = 0; e < 2; e++) {
                S[aI][e]   *= sc;
                S[aI][2+e] *= sc;
                if (kb == qb) {
                    if (colb0 + e > r0loc)     S[aI][e]   = -1e30f;
                    if (colb0 + e > r0loc + 8) S[aI][2+e] = -1e30f;
                }
            }
        }

        // ---- online softmax (rows r0loc and r0loc+8) ----
        float alpha[2];
        #pragma unroll
        for (int hrow = 0; hrow < 2; hrow++) {
            float mx = -1e30f;
            #pragma unroll
            for (int aI = 0; aI < 8; aI++)
                mx = fmaxf(mx, fmaxf(S[aI][2*hrow], S[aI][2*hrow+1]));
            mx = fmaxf(mx, __shfl_xor_sync(0xffffffffu, mx, 1));
            mx = fmaxf(mx, __shfl_xor_sync(0xffffffffu, mx, 2));
            float mn = fmaxf(mr[hrow], mx);
            alpha[hrow] = __expf(mr[hrow] - mn);
            mr[hrow] = mn;
            float rs = 0.f;
            #pragma unroll
            for (int aI = 0; aI < 8; aI++) {
                S[aI][2*hrow]   = __expf(S[aI][2*hrow]   - mn);
                S[aI][2*hrow+1] = __expf(S[aI][2*hrow+1] - mn);
                rs += S[aI][2*hrow] + S[aI][2*hrow+1];
            }
            rs += __shfl_xor_sync(0xffffffffu, rs, 1);
            rs += __shfl_xor_sync(0xffffffffu, rs, 2);
            lr[hrow] = lr[hrow] * alpha[hrow] + rs;
        }
        #pragma unroll
        for (int aI = 0; aI < 8; aI++) {
            O[aI][0] *= alpha[0]; O[aI][1] *= alpha[0];
            O[aI][2] *= alpha[1]; O[aI][3] *= alpha[1];
        }

        // ---- O += P V (fp16, P packed from S accums) ----
        #pragma unroll
        for (int j = 0; j < 4; j++) {
            uint32_t pa[4];
            __half2 t0 = __floats2half2_rn(S[2*j][0],   S[2*j][1]);
            __half2 t1 = __floats2half2_rn(S[2*j][2],   S[2*j][3]);
            __half2 t2 = __floats2half2_rn(S[2*j+1][0], S[2*j+1][1]);
            __half2 t3 = __floats2half2_rn(S[2*j+1][2], S[2*j+1][3]);
            pa[0] = *(uint32_t*)&t0; pa[1] = *(uint32_t*)&t1;
            pa[2] = *(uint32_t*)&t2; pa[3] = *(uint32_t*)&t3;
            const int rowV = 16*j + (lane & 7) + 8*((lane >> 3) & 1);
            #pragma unroll
            for (int q = 0; q < 4; q++) {
                uint32_t vb[4];
                ldm4t(vb, av + (uint32_t)(rowV*144 + (2*q + ((lane >> 4) & 1))*16));
                mma_f16(O[2*q],   pa, vb);
                mma_f16(O[2*q+1], pa, vb + 2);
            }
        }
    }

    // ---- normalize + store fp16 to g_yh [m][h*64+d] ----
    const float inv0 = 1.0f / lr[0];
    const float inv1 = 1.0f / lr[1];
    const int b = bh >> 4;
    const int h = bh & 15;
    const int t0g = q0 + r0loc;
    #pragma unroll
    for (int aI = 0; aI < 8; aI++) {
        int d = 16*(aI >> 1) + 8*(aI & 1) + 2*(lane & 3);
        __half2 h0 = __floats2half2_rn(O[aI][0]*inv0, O[aI][1]*inv0);
        __half2 h1 = __floats2half2_rn(O[aI][2]*inv1, O[aI][3]*inv1);
        *(__half2*)&g_yh[((size_t)(b*Tz + t0g))*Cz + h*Dz + d]     = h0;
        *(__half2*)&g_yh[((size_t)(b*Tz + t0g + 8))*Cz + h*Dz + d] = h1;
    }
}

// ---------------------------------------------------------------------------
extern "C" void kernel_launch(void* const* d_in, const int* in_sizes, int n_in,
                              void* d_out, int out_size)
{
    const float* x     = (const float*)d_in[0];
    const float* Wqkv  = (const float*)d_in[1];
    const float* bqkv  = (const float*)d_in[2];
    const float* Wproj = (const float*)d_in[3];
    const float* bproj = (const float*)d_in[4];
    float* out = (float*)d_out;

    // 1) prep: x -> fp16 ; W^T -> fp16
    cvt_x_kernel<<<2048, 256>>>(x);
    transpose_cvt_kernel<<<dim3(3*Cz/32, Cz/32), dim3(32,8)>>>(Wqkv, 3*Cz, 0);
    transpose_cvt_kernel<<<dim3(Cz/32,   Cz/32), dim3(32,8)>>>(Wproj, Cz, 1);

    // 2) QKV GEMM (fp16 HMMA, BK=32) -> scatter fp16 into g_qh/g_kh/g_vh
    mma_gemm_kernel<<<dim3(3*Cz/256, Mz/128), 256>>>(0, 3*Cz, bqkv, nullptr);

    // 3) causal flash attention (fp16 HMMA, 64-row CTAs) -> g_yh
    attn_kernel<<<dim3(Tz/64, Bz*Hz), 128>>>();

    // 4) proj GEMM (fp16 HMMA, BK=32) -> d_out
    mma_gemm_kernel<<<dim3(Cz/256, Mz/128), 256>>>(1, Cz, bproj, out);
}

// round 16
// speedup vs baseline: 1.1426x; 1.1426x over previous
#include <cuda_runtime.h>
#include <cuda_fp16.h>
#include <cstdint>

// Problem constants (fixed shapes from reference)
#define Bz 8
#define Tz 1024
#define Cz 1024
#define Hz 16
#define Dz 64
#define Mz (Bz*Tz)   // 8192

// ---- mma / ldmatrix / cp.async helpers (arch-agnostic PTX) -----------------
__device__ __forceinline__ uint32_t smem_to_u32(const void* p) {
    uint32_t a;
    asm("{ .reg .u64 t; cvta.to.shared.u64 t, %1; cvt.u32.u64 %0, t; }" : "=r"(a) : "l"(p));
    return a;
}
__device__ __forceinline__ void ldm4(uint32_t* r, uint32_t addr) {
    asm volatile("ldmatrix.sync.aligned.m8n8.x4.shared.b16 {%0,%1,%2,%3}, [%4];"
                 : "=r"(r[0]), "=r"(r[1]), "=r"(r[2]), "=r"(r[3]) : "r"(addr));
}
__device__ __forceinline__ void ldm4t(uint32_t* r, uint32_t addr) {
    asm volatile("ldmatrix.sync.aligned.m8n8.x4.trans.shared.b16 {%0,%1,%2,%3}, [%4];"
                 : "=r"(r[0]), "=r"(r[1]), "=r"(r[2]), "=r"(r[3]) : "r"(addr));
}
__device__ __forceinline__ void mma_f16(float* c, const uint32_t* a, const uint32_t* b) {
    asm volatile("mma.sync.aligned.m16n8k16.row.col.f32.f16.f16.f32 "
                 "{%0,%1,%2,%3},{%4,%5,%6,%7},{%8,%9},{%0,%1,%2,%3};"
                 : "+f"(c[0]), "+f"(c[1]), "+f"(c[2]), "+f"(c[3])
                 : "r"(a[0]), "r"(a[1]), "r"(a[2]), "r"(a[3]), "r"(b[0]), "r"(b[1]));
}
__device__ __forceinline__ void cp16(uint32_t s, const void* g) {
    asm volatile("cp.async.cg.shared.global [%0], [%1], 16;" :: "r"(s), "l"(g));
}
#define CP_COMMIT() asm volatile("cp.async.commit_group;" ::: "memory")
#define CP_WAIT1()  asm volatile("cp.async.wait_group 1;" ::: "memory")
#define CP_WAIT0()  asm volatile("cp.async.wait_group 0;" ::: "memory")

// ---- scratch (device globals; no allocation allowed) -----------------------
__device__ __align__(16) __half g_qh[Bz*Hz*Tz*Dz];   // [b][h][t][d] fp16
__device__ __align__(16) __half g_kh[Bz*Hz*Tz*Dz];
__device__ __align__(16) __half g_vh[Bz*Hz*Tz*Dz];
__device__ __align__(16) __half g_yh[Mz*Cz];         // attn out fp16, [m][h*64+d]
__device__ __align__(16) __half g_xh[Mz*Cz];         // x fp16, [M][1024]
__device__ __align__(16) __half g_wqkvh[3*Cz*Cz];    // Wqkv^T fp16 [3072][1024]
__device__ __align__(16) __half g_wprjh[Cz*Cz];      // Wproj^T fp16 [1024][1024]

// ---------------------------------------------------------------------------
// Prep: x fp32 -> fp16
// ---------------------------------------------------------------------------
__global__ void __launch_bounds__(256) cvt_x_kernel(const float* __restrict__ in)
{
    const int n4 = Mz*Cz/4;
    for (int i = blockIdx.x * blockDim.x + threadIdx.x; i < n4; i += gridDim.x * blockDim.x) {
        float4 v = ((const float4*)in)[i];
        __half2 h0 = __floats2half2_rn(v.x, v.y);
        __half2 h1 = __floats2half2_rn(v.z, v.w);
        ((uint2*)g_xh)[i] = make_uint2(*(uint32_t*)&h0, *(uint32_t*)&h1);
    }
}

// ---------------------------------------------------------------------------
// Prep: W [1024 k][N n] fp32 -> Wt [N][1024] fp16 (transpose + convert)
// ---------------------------------------------------------------------------
__global__ void __launch_bounds__(256) transpose_cvt_kernel(
    const float* __restrict__ W, int N, int which)
{
    __shared__ float t[32][33];
    __half* T = which ? g_wprjh : g_wqkvh;
    const int n0 = blockIdx.x * 32, k0 = blockIdx.y * 32;
    const int tx = threadIdx.x, ty = threadIdx.y;   // (32, 8)
    #pragma unroll
    for (int j = ty; j < 32; j += 8)
        t[j][tx] = W[(size_t)(k0 + j) * N + n0 + tx];
    __syncthreads();
    #pragma unroll
    for (int j = ty; j < 32; j += 8)
        T[(size_t)(n0 + j) * 1024 + k0 + tx] = __float2half(t[tx][j]);
}

// ---------------------------------------------------------------------------
// fp16 GEMM via mma.sync — EXACT R11/R12 version (best measured, at floor).
// CTA tile 128x256, BK=16, 3-stage cp.async pipeline, ONE barrier per k-step.
// Smem XOR swizzle (chunk ^= (row>>2)&1), row stride 32B. Ping-ponged A frags.
// ---------------------------------------------------------------------------
#define STG_A   4096          // 128 rows * 32B
#define STG_SZ  12288         // A + B(256*32)

__global__ void __launch_bounds__(256) mma_gemm_kernel(
    int mode, int N, const float* __restrict__ bias, float* __restrict__ out)
{
    __shared__ __align__(16) char smem[3*STG_SZ];   // 36864 B

    const int tid  = threadIdx.x;
    const int lane = tid & 31;
    const int wid  = tid >> 5;
    const int warp_m = wid & 1;        // 2 m-warps (64 rows each)
    const int warp_n = wid >> 1;       // 4 n-warps (64 cols each)
    const int m0 = blockIdx.y * 128;
    const int n0 = blockIdx.x * 256;

    const __half* Ap = mode ? g_yh : g_xh;
    const __half* Bp = mode ? g_wprjh : g_wqkvh;

    const int gr = tid >> 1;            // 0..127
    const int gh = tid & 1;             // which 16B chunk of the 32B k16 row
    const __half* gA  = Ap + (size_t)(m0 + gr) * 1024 + gh*8;
    const __half* gB0 = Bp + (size_t)(n0 + gr) * 1024 + gh*8;
    const __half* gB1 = Bp + (size_t)(n0 + 128 + gr) * 1024 + gh*8;

    const uint32_t sbase = smem_to_u32(smem);
    const int swg = (gr >> 2) & 1;
    const uint32_t stA  = (uint32_t)(gr*32 + (gh ^ swg)*16);
    const uint32_t stB0 = (uint32_t)(STG_A + gr*32 + (gh ^ swg)*16);
    const uint32_t stB1 = stB0 + 4096;

    const int rbA = warp_m*64 + (lane & 7) + 8*((lane >> 3) & 1);
    const uint32_t chA = (uint32_t)((((lane >> 4) & 1) ^ ((rbA >> 2) & 1)) * 16);
    const int rbB = warp_n*64 + (lane & 7) + 8*((lane >> 4) & 1);
    const uint32_t chB = (uint32_t)((((lane >> 3) & 1) ^ ((rbB >> 2) & 1)) * 16);

    float acc[4][8][4];
    #pragma unroll
    for (int i = 0; i < 4; i++)
        #pragma unroll
        for (int j = 0; j < 8; j++)
            #pragma unroll
            for (int r = 0; r < 4; r++) acc[i][j][r] = 0.f;

    #pragma unroll
    for (int pk = 0; pk < 2; pk++) {
        const uint32_t so = (uint32_t)pk * STG_SZ;
        const int go = pk * 16;
        cp16(sbase + so + stA,  gA  + go);
        cp16(sbase + so + stB0, gB0 + go);
        cp16(sbase + so + stB1, gB1 + go);
        CP_COMMIT();
    }

    int s_cur = 0, s_nxt = 2;
    for (int kc = 0; kc < 64; kc++) {
        CP_WAIT1();
        __syncthreads();

        if (kc < 62) {
            const uint32_t so = (uint32_t)s_nxt * STG_SZ;
            const int go = (kc + 2) * 16;
            cp16(sbase + so + stA,  gA  + go);
            cp16(sbase + so + stB0, gB0 + go);
            cp16(sbase + so + stB1, gB1 + go);
        }
        CP_COMMIT();

        const uint32_t bufo = (uint32_t)s_cur * STG_SZ;

        uint32_t bf[4][4];
        #pragma unroll
        for (int p = 0; p < 4; p++)
            ldm4(bf[p], sbase + bufo + STG_A + (uint32_t)((rbB + 16*p) * 32) + chB);

        uint32_t af[2][4];
        ldm4(af[0], sbase + bufo + (uint32_t)(rbA * 32) + chA);
        #pragma unroll
        for (int mi = 0; mi < 4; mi++) {
            if (mi < 3)
                ldm4(af[(mi+1) & 1], sbase + bufo + (uint32_t)((rbA + 16*(mi+1)) * 32) + chA);
            #pragma unroll
            for (int ni = 0; ni < 8; ni++)
                mma_f16(acc[mi][ni], af[mi & 1], &bf[ni >> 1][2*(ni & 1)]);
        }

        s_cur = (s_cur == 2) ? 0 : s_cur + 1;
        s_nxt = (s_nxt == 2) ? 0 : s_nxt + 1;
    }

    const int g4 = lane >> 2;
    const int c2 = 2 * (lane & 3);
    #pragma unroll
    for (int mi = 0; mi < 4; mi++) {
        #pragma unroll
        for (int ni = 0; ni < 8; ni++) {
            int m = m0 + warp_m*64 + mi*16 + g4;
            int n = n0 + warp_n*64 + ni*8 + c2;
            float2 bv = *(const float2*)&bias[n];
            float2 v0 = make_float2(acc[mi][ni][0] + bv.x, acc[mi][ni][1] + bv.y);
            float2 v1 = make_float2(acc[mi][ni][2] + bv.x, acc[mi][ni][3] + bv.y);
            if (mode == 1) {
                *(float2*)&out[(size_t)m * N + n]     = v0;
                *(float2*)&out[(size_t)(m+8) * N + n] = v1;
            } else {
                int which = n >> 10;            // 0=q 1=k 2=v
                int h = (n >> 6) & 15;
                int d = n & 63;
                __half* dst = (which == 0) ? g_qh : ((which == 1) ? g_kh : g_vh);
                int b0i = m >> 10,  t0 = m & 1023;
                int b1i = (m+8) >> 10, t1 = (m+8) & 1023;
                __half2 h0 = __floats2half2_rn(v0.x, v0.y);
                __half2 h1 = __floats2half2_rn(v1.x, v1.y);
                *(__half2*)&dst[((size_t)(b0i*Hz + h)*Tz + t0)*Dz + d] = h0;
                *(__half2*)&dst[((size_t)(b1i*Hz + h)*Tz + t1)*Dz + d] = h1;
            }
        }
    }
}

// ---------------------------------------------------------------------------
// Flash attention v2 (causal), all-fp16 tensor-core path — EXACT R12 math,
// with LONGEST-JOB-FIRST scheduling: qb = 15 - blockIdx.x so the heaviest
// causal CTAs (most key blocks) launch in the first wave.
// 64 q-rows per CTA, 4 warps; K/V cp.async double-buffered, ONE barrier/iter.
// ---------------------------------------------------------------------------
#define ASTRIDE 72
#define ATILE (64*ASTRIDE)    // halves per tile (9216 B)

__global__ void __launch_bounds__(128) attn_kernel()
{
    __shared__ __align__(16) __half sT[2][ATILE];
    __shared__ __align__(16) __half sV[2][ATILE];

    const int tid  = threadIdx.x;
    const int lane = tid & 31;
    const int w    = tid >> 5;         // 0..3
    const int qb   = (int)(gridDim.x - 1) - (int)blockIdx.x;   // heavy CTAs first
    const int bh   = blockIdx.y;
    const int q0   = qb * 64;

    const uint32_t aT[2] = { smem_to_u32(sT[0]), smem_to_u32(sT[1]) };
    const uint32_t aV[2] = { smem_to_u32(sV[0]), smem_to_u32(sV[1]) };

    // ---- load Q tile into sT[0] (plain copy), hoist frags ----
    {
        const uint4* qg = (const uint4*)(g_qh + ((size_t)bh*Tz + q0)*Dz);
        #pragma unroll
        for (int u = 0; u < 4; u++) {
            int idx4 = tid + 128*u;
            int r = idx4 >> 3, d8 = idx4 & 7;
            *(uint4*)&sT[0][r*ASTRIDE + d8*8] = qg[idx4];
        }
    }
    __syncthreads();

    uint32_t qf[4][4];
    {
        const int rowA = 16*w + (lane & 7) + 8*((lane >> 3) & 1);
        const int colb = ((lane >> 4) & 1) * 16;
        #pragma unroll
        for (int j = 0; j < 4; j++)
            ldm4(qf[j], aT[0] + (uint32_t)(rowA*144 + j*32 + colb));
    }
    __syncthreads();   // Q smem dead; cp.async may overwrite sT[0]

    // ---- prologue: issue K/V for kb=0 into buffer 0 ----
    {
        const __half* kg = g_kh + (size_t)bh*Tz*Dz;
        const __half* vg = g_vh + (size_t)bh*Tz*Dz;
        #pragma unroll
        for (int u = 0; u < 4; u++) {
            int idx4 = tid + 128*u;
            int r = idx4 >> 3, d8 = idx4 & 7;
            uint32_t so = (uint32_t)(r*144 + d8*16);
            cp16(aT[0] + so, kg + idx4*8);
            cp16(aV[0] + so, vg + idx4*8);
        }
        CP_COMMIT();
    }

    float mr[2] = {-1e30f, -1e30f};
    float lr[2] = {0.f, 0.f};
    float O[8][4];
    #pragma unroll
    for (int aI = 0; aI < 8; aI++)
        #pragma unroll
        for (int e = 0; e < 4; e++) O[aI][e] = 0.f;

    const int r0loc = 16*w + (lane >> 2);   // block-local row for softmax/mask

    for (int kb = 0; kb <= qb; kb++) {
        CP_WAIT0();
        __syncthreads();

        // prefetch kb+1 into the other buffer (its readers finished last iter)
        if (kb < qb) {
            const int nb = (kb + 1) & 1;
            const __half* kg = g_kh + ((size_t)bh*Tz + (kb+1)*64)*Dz;
            const __half* vg = g_vh + ((size_t)bh*Tz + (kb+1)*64)*Dz;
            #pragma unroll
            for (int u = 0; u < 4; u++) {
                int idx4 = tid + 128*u;
                int r = idx4 >> 3, d8 = idx4 & 7;
                uint32_t so = (uint32_t)(r*144 + d8*16);
                cp16(aT[nb] + so, kg + idx4*8);
                cp16(aV[nb] + so, vg + idx4*8);
            }
            CP_COMMIT();
        }

        const uint32_t a0 = aT[kb & 1];
        const uint32_t av = aV[kb & 1];

        // ---- S = Q K^T (single fp16 pass) ----
        float S[8][4];
        #pragma unroll
        for (int aI = 0; aI < 8; aI++)
            #pragma unroll
            for (int e = 0; e < 4; e++) S[aI][e] = 0.f;

        const int rowB = (lane & 7) + 8*((lane >> 4) & 1);
        const int colbB = ((lane >> 3) & 1) * 16;
        #pragma unroll
        for (int j = 0; j < 4; j++) {
            #pragma unroll
            for (int p = 0; p < 4; p++) {
                uint32_t kf[4];
                ldm4(kf, a0 + (uint32_t)((16*p + rowB)*144 + j*32 + colbB));
                mma_f16(S[2*p],   qf[j], kf);
                mma_f16(S[2*p+1], qf[j], kf + 2);
            }
        }

        // ---- scale + causal mask (diagonal block only) ----
        const float sc = 0.125f;
        #pragma unroll
        for (int aI = 0; aI < 8; aI++) {
            int colb0 = 16*(aI >> 1) + 8*(aI & 1) + 2*(lane & 3);
            #pragma unroll
            for (int e = 0; e < 2; e++) {
                S[aI][e]   *= sc;
                S[aI][2+e] *= sc;
                if (kb == qb) {
                    if (colb0 + e > r0loc)     S[aI][e]   = -1e30f;
                    if (colb0 + e > r0loc + 8) S[aI][2+e] = -1e30f;
                }
            }
        }

        // ---- online softmax (rows r0loc and r0loc+8) ----
        float alpha[2];
        #pragma unroll
        for (int hrow = 0; hrow < 2; hrow++) {
            float mx = -1e30f;
            #pragma unroll
            for (int aI = 0; aI < 8; aI++)
                mx = fmaxf(mx, fmaxf(S[aI][2*hrow], S[aI][2*hrow+1]));
            mx = fmaxf(mx, __shfl_xor_sync(0xffffffffu, mx, 1));
            mx = fmaxf(mx, __shfl_xor_sync(0xffffffffu, mx, 2));
            float mn = fmaxf(mr[hrow], mx);
            alpha[hrow] = __expf(mr[hrow] - mn);
            mr[hrow] = mn;
            float rs = 0.f;
            #pragma unroll
            for (int aI = 0; aI < 8; aI++) {
                S[aI][2*hrow]   = __expf(S[aI][2*hrow]   - mn);
                S[aI][2*hrow+1] = __expf(S[aI][2*hrow+1] - mn);
                rs += S[aI][2*hrow] + S[aI][2*hrow+1];
            }
            rs += __shfl_xor_sync(0xffffffffu, rs, 1);
            rs += __shfl_xor_sync(0xffffffffu, rs, 2);
            lr[hrow] = lr[hrow] * alpha[hrow] + rs;
        }
        #pragma unroll
        for (int aI = 0; aI < 8; aI++) {
            O[aI][0] *= alpha[0]; O[aI][1] *= alpha[0];
            O[aI][2] *= alpha[1]; O[aI][3] *= alpha[1];
        }

        // ---- O += P V (fp16, P packed from S accums) ----
        #pragma unroll
        for (int j = 0; j < 4; j++) {
            uint32_t pa[4];
            __half2 t0 = __floats2half2_rn(S[2*j][0],   S[2*j][1]);
            __half2 t1 = __floats2half2_rn(S[2*j][2],   S[2*j][3]);
            __half2 t2 = __floats2half2_rn(S[2*j+1][0], S[2*j+1][1]);
            __half2 t3 = __floats2half2_rn(S[2*j+1][2], S[2*j+1][3]);
            pa[0] = *(uint32_t*)&t0; pa[1] = *(uint32_t*)&t1;
            pa[2] = *(uint32_t*)&t2; pa[3] = *(uint32_t*)&t3;
            const int rowV = 16*j + (lane & 7) + 8*((lane >> 3) & 1);
            #pragma unroll
            for (int q = 0; q < 4; q++) {
                uint32_t vb[4];
                ldm4t(vb, av + (uint32_t)(rowV*144 + (2*q + ((lane >> 4) & 1))*16));
                mma_f16(O[2*q],   pa, vb);
                mma_f16(O[2*q+1], pa, vb + 2);
            }
        }
    }

    // ---- normalize + store fp16 to g_yh [m][h*64+d] ----
    const float inv0 = 1.0f / lr[0];
    const float inv1 = 1.0f / lr[1];
    const int b = bh >> 4;
    const int h = bh & 15;
    const int t0g = q0 + r0loc;
    #pragma unroll
    for (int aI = 0; aI < 8; aI++) {
        int d = 16*(aI >> 1) + 8*(aI & 1) + 2*(lane & 3);
        __half2 h0 = __floats2half2_rn(O[aI][0]*inv0, O[aI][1]*inv0);
        __half2 h1 = __floats2half2_rn(O[aI][2]*inv1, O[aI][3]*inv1);
        *(__half2*)&g_yh[((size_t)(b*Tz + t0g))*Cz + h*Dz + d]     = h0;
        *(__half2*)&g_yh[((size_t)(b*Tz + t0g + 8))*Cz + h*Dz + d] = h1;
    }
}

// ---------------------------------------------------------------------------
extern "C" void kernel_launch(void* const* d_in, const int* in_sizes, int n_in,
                              void* d_out, int out_size)
{
    const float* x     = (const float*)d_in[0];
    const float* Wqkv  = (const float*)d_in[1];
    const float* bqkv  = (const float*)d_in[2];
    const float* Wproj = (const float*)d_in[3];
    const float* bproj = (const float*)d_in[4];
    float* out = (float*)d_out;

    // 1) prep: x -> fp16 ; W^T -> fp16
    cvt_x_kernel<<<2048, 256>>>(x);
    transpose_cvt_kernel<<<dim3(3*Cz/32, Cz/32), dim3(32,8)>>>(Wqkv, 3*Cz, 0);
    transpose_cvt_kernel<<<dim3(Cz/32,   Cz/32), dim3(32,8)>>>(Wproj, Cz, 1);

    // 2) QKV GEMM (fp16 HMMA) -> scatter fp16 into g_qh/g_kh/g_vh
    mma_gemm_kernel<<<dim3(3*Cz/256, Mz/128), 256>>>(0, 3*Cz, bqkv, nullptr);

    // 3) causal flash attention (fp16 HMMA, longest-job-first) -> g_yh
    attn_kernel<<<dim3(Tz/64, Bz*Hz), 128>>>();

    // 4) proj GEMM (fp16 HMMA) -> d_out
    mma_gemm_kernel<<<dim3(Cz/256, Mz/128), 256>>>(1, Cz, bproj, out);
}